// round 13
// baseline (speedup 1.0000x reference)
#include <cuda_runtime.h>

#define BATCH   8192
#define INS     64
#define OUTS    64
#define BTILE   8              // batch rows per block
#define NPAIR   4              // f32x2 batch pairs per thread
#define QSPLIT  4              // i-range split across warp groups
#define ICHUNK  (INS/QSPLIT)   // 16

// Pre-DUPLICATED params: each float4 = (v, v, w, w) so LDG.128 yields
// aligned (v,v) register pairs consumed directly by fma.f32x2 — zero MOVs.
// idx = i*OUTS + o.
__device__ float4 g_D0[INS * OUTS];  // (w1h0, w1h0, w1h1, w1h1)
__device__ float4 g_D1[INS * OUTS];  // (b1h0, b1h0, b1h1, b1h1)
__device__ float4 g_D2[INS * OUTS];  // (wA,  wA,  wB,  wB )  [w2 k0]
__device__ float4 g_D3[INS * OUTS];  // (wC,  wC,  wD,  wD )  [w2 k1]
__device__ float4 g_D4[INS * OUTS];  // (b2k0,b2k0,b2k1,b2k1)
__device__ float4 g_D5[INS * OUTS];  // (w3k0,w3k0,w3k1,w3k1)
__device__ float  g_SB3[OUTS];       // sum_i b3[i][o]

// Packed f32x2 FMA (sm_103a — only reachable via PTX).
__device__ __forceinline__ float2 ffma2(float2 a, float2 b, float2 c) {
    float2 d;
    asm("{\n\t"
        ".reg .b64 ra, rb, rc, rd;\n\t"
        "mov.b64 ra, {%2, %3};\n\t"
        "mov.b64 rb, {%4, %5};\n\t"
        "mov.b64 rc, {%6, %7};\n\t"
        "fma.rn.f32x2 rd, ra, rb, rc;\n\t"
        "mov.b64 {%0, %1}, rd;\n\t"
        "}"
        : "=f"(d.x), "=f"(d.y)
        : "f"(a.x), "f"(a.y), "f"(b.x), "f"(b.y), "f"(c.x), "f"(c.y));
    return d;
}

__device__ __forceinline__ float2 relu2(float2 a) {
    a.x = fmaxf(a.x, 0.0f);
    a.y = fmaxf(a.y, 0.0f);
    return a;
}

__device__ __forceinline__ float2 lo2(float4 p) { return make_float2(p.x, p.y); }
__device__ __forceinline__ float2 hi2(float4 p) { return make_float2(p.z, p.w); }

__global__ void __launch_bounds__(256)
pack_kernel(const float2* __restrict__ w1, const float2* __restrict__ b1,
            const float4* __restrict__ w2, const float2* __restrict__ b2,
            const float2* __restrict__ w3, const float*  __restrict__ b3)
{
    const int t = blockIdx.x * 256 + threadIdx.x;   // 0..4095 (one per (i,o))
    const float2 W1 = w1[t], B1 = b1[t], B2 = b2[t], W3 = w3[t];
    const float4 W2 = w2[t];

    g_D0[t] = make_float4(W1.x, W1.x, W1.y, W1.y);
    g_D1[t] = make_float4(B1.x, B1.x, B1.y, B1.y);
    g_D2[t] = make_float4(W2.x, W2.x, W2.y, W2.y);
    g_D3[t] = make_float4(W2.z, W2.z, W2.w, W2.w);
    g_D4[t] = make_float4(B2.x, B2.x, B2.y, B2.y);
    g_D5[t] = make_float4(W3.x, W3.x, W3.y, W3.y);

    if (t < OUTS) {
        float s = 0.0f;
        for (int i = 0; i < INS; i++) s += b3[i * OUTS + t];
        g_SB3[t] = s;
    }
}

__global__ void __launch_bounds__(256, 4)
kan_kernel(const float* __restrict__ x, float* __restrict__ out)
{
    __shared__ float xs[INS * BTILE];                 // xs[i*8 + b]
    __shared__ float part[QSPLIT * BTILE * OUTS];     // part[q][b][o]

    const int tid = threadIdx.x;
    const int o   = tid & (OUTS - 1);     // 0..63
    const int q   = tid >> 6;             // 0..3 : i-range quarter
    const int b0  = blockIdx.x * BTILE;

    // Stage x tile transposed: xs[i][b]. Coalesced global reads.
    #pragma unroll
    for (int k = 0; k < (BTILE * INS) / 256; k++) {
        int idx = k * 256 + tid;
        int b = idx >> 6;
        int i = idx & (INS - 1);
        xs[i * BTILE + b] = x[(b0 + b) * INS + i];
    }
    __syncthreads();

    float2 acc[NPAIR];
    #pragma unroll
    for (int j = 0; j < NPAIR; j++) acc[j] = make_float2(0.0f, 0.0f);

    const int i_lo = q * ICHUNK;
    const int base = i_lo * OUTS + o;

    // Full distance-1 prefetch — R5's proven latency plan.
    float4 nD0 = __ldg(&g_D0[base]);
    float4 nD1 = __ldg(&g_D1[base]);
    float4 nD2 = __ldg(&g_D2[base]);
    float4 nD3 = __ldg(&g_D3[base]);
    float4 nD4 = __ldg(&g_D4[base]);
    float4 nD5 = __ldg(&g_D5[base]);

    #pragma unroll 2
    for (int ii = 0; ii < ICHUNK; ii++) {
        const float4 D0 = nD0, D1 = nD1, D2 = nD2;
        const float4 D3 = nD3, D4 = nD4, D5 = nD5;

        // prefetch next (wraps on last iter — harmless redundant load)
        const int nidx = base + ((ii + 1) & (ICHUNK - 1)) * OUTS;
        nD0 = __ldg(&g_D0[nidx]);
        nD1 = __ldg(&g_D1[nidx]);
        nD2 = __ldg(&g_D2[nidx]);
        nD3 = __ldg(&g_D3[nidx]);
        nD4 = __ldg(&g_D4[nidx]);
        nD5 = __ldg(&g_D5[nidx]);

        const float* xrow = &xs[(i_lo + ii) * BTILE];

        #pragma unroll
        for (int j = 0; j < NPAIR; j++) {
            // LDS.64, warp-uniform -> broadcast, conflict-free
            float2 xv = *(const float2*)(xrow + 2 * j);
            // Operands come straight from LDG.128 quads — no broadcast MOVs.
            float2 t0 = relu2(ffma2(xv, lo2(D0), lo2(D1)));
            float2 t1 = relu2(ffma2(xv, hi2(D0), hi2(D1)));
            float2 u0 = relu2(ffma2(t0, lo2(D2), ffma2(t1, hi2(D2), lo2(D4))));
            float2 u1 = relu2(ffma2(t0, lo2(D3), ffma2(t1, hi2(D3), hi2(D4))));
            acc[j] = ffma2(u0, lo2(D5), ffma2(u1, hi2(D5), acc[j]));
        }
    }

    // Write q-partials (b3 added at the final store).
    float* pq = &part[q * BTILE * OUTS];
    #pragma unroll
    for (int j = 0; j < NPAIR; j++) {
        pq[(2 * j)     * OUTS + o] = acc[j].x;
        pq[(2 * j + 1) * OUTS + o] = acc[j].y;
    }
    __syncthreads();

    // Reduce the four quarters + per-o b3 sum; coalesced float2 store.
    {
        const int f  = tid * 2;                // 0..510
        const int oo = f & (OUTS - 1);
        const float2* p2 = (const float2*)part;
        float2 a = p2[tid];
        float2 b = p2[256 + tid];
        float2 c = p2[512 + tid];
        float2 d = p2[768 + tid];
        float2 r;
        r.x = (a.x + b.x) + (c.x + d.x) + g_SB3[oo];
        r.y = (a.y + b.y) + (c.y + d.y) + g_SB3[oo + 1];
        *(float2*)&out[b0 * OUTS + f] = r;
    }
}

extern "C" void kernel_launch(void* const* d_in, const int* in_sizes, int n_in,
                              void* d_out, int out_size)
{
    const float* x  = (const float*)d_in[0];
    const float* w1 = (const float*)d_in[1];
    const float* b1 = (const float*)d_in[2];
    const float* w2 = (const float*)d_in[3];
    const float* b2 = (const float*)d_in[4];
    const float* w3 = (const float*)d_in[5];
    const float* b3 = (const float*)d_in[6];
    float* out = (float*)d_out;

    pack_kernel<<<(INS * OUTS) / 256, 256>>>(
        (const float2*)w1, (const float2*)b1, (const float4*)w2,
        (const float2*)b2, (const float2*)w3, b3);

    kan_kernel<<<BATCH / BTILE, 256>>>(x, out);
}

// round 14
// speedup vs baseline: 1.9518x; 1.9518x over previous
#include <cuda_runtime.h>

#define BATCH   8192
#define INS     64
#define OUTS    64
#define BTILE   8              // batch rows per block
#define NPAIR   4              // f32x2 pairs per thread (8 batch rows)
#define QSPLIT  4              // i-range split across warp groups
#define ICHUNK  (INS/QSPLIT)   // 16

// Packed f32x2 FMA (sm_103a FFMA2 — only reachable via PTX).
__device__ __forceinline__ float2 ffma2(float2 a, float2 b, float2 c) {
    float2 d;
    asm("{\n\t"
        ".reg .b64 ra, rb, rc, rd;\n\t"
        "mov.b64 ra, {%2, %3};\n\t"
        "mov.b64 rb, {%4, %5};\n\t"
        "mov.b64 rc, {%6, %7};\n\t"
        "fma.rn.f32x2 rd, ra, rb, rc;\n\t"
        "mov.b64 {%0, %1}, rd;\n\t"
        "}"
        : "=f"(d.x), "=f"(d.y)
        : "f"(a.x), "f"(a.y), "f"(b.x), "f"(b.y), "f"(c.x), "f"(c.y));
    return d;
}

__device__ __forceinline__ float2 relu2(float2 a) {
    a.x = fmaxf(a.x, 0.0f);
    a.y = fmaxf(a.y, 0.0f);
    return a;
}

__device__ __forceinline__ float2 bcast2(float v) { return make_float2(v, v); }

__global__ void __launch_bounds__(256, 4)
kan_kernel(const float* __restrict__ x,
           const float* __restrict__ w1, const float* __restrict__ b1,
           const float* __restrict__ w2, const float* __restrict__ b2,
           const float* __restrict__ w3, const float* __restrict__ b3,
           float* __restrict__ out)
{
    __shared__ float xs[INS * BTILE];                 // xs[i*8 + b]
    __shared__ float part[QSPLIT * BTILE * OUTS];     // part[q][b][o]

    const int tid = threadIdx.x;
    const int o   = tid & (OUTS - 1);     // 0..63
    const int q   = tid >> 6;             // 0..3 : i-range quarter
    const int b0  = blockIdx.x * BTILE;

    // Stage x tile transposed: xs[i][b]. Coalesced global reads.
    #pragma unroll
    for (int k = 0; k < (BTILE * INS) / 256; k++) {
        int idx = k * 256 + tid;
        int b = idx >> 6;
        int i = idx & (INS - 1);
        xs[i * BTILE + b] = x[(b0 + b) * INS + i];
    }
    __syncthreads();

    float2 acc[NPAIR];
    #pragma unroll
    for (int j = 0; j < NPAIR; j++) acc[j] = make_float2(0.0f, 0.0f);
    float sb3 = 0.0f;

    const float2* __restrict__ w1v = (const float2*)w1;
    const float2* __restrict__ b1v = (const float2*)b1;
    const float4* __restrict__ w2v = (const float4*)w2;
    const float2* __restrict__ b2v = (const float2*)b2;
    const float2* __restrict__ w3v = (const float2*)w3;

    const int i_lo = q * ICHUNK;

    // Software pipeline: params for iteration ii+1 load during compute of ii.
    int po = i_lo * OUTS + o;
    float2 nW1 = __ldg(w1v + po);
    float2 nB1 = __ldg(b1v + po);
    float4 nW2 = __ldg(w2v + po);
    float2 nB2 = __ldg(b2v + po);
    float2 nW3 = __ldg(w3v + po);
    float  nB3 = __ldg(b3  + po);

    #pragma unroll 8
    for (int ii = 0; ii < ICHUNK; ii++) {
        const float2 W1 = nW1, B1 = nB1, B2 = nB2, W3 = nW3;
        const float4 W2 = nW2;
        sb3 += nB3;

        // prefetch next (wraps on last iter — harmless redundant load)
        const int pn = (i_lo + ((ii + 1) & (ICHUNK - 1))) * OUTS + o;
        nW1 = __ldg(w1v + pn);
        nB1 = __ldg(b1v + pn);
        nW2 = __ldg(w2v + pn);
        nB2 = __ldg(b2v + pn);
        nW3 = __ldg(w3v + pn);
        nB3 = __ldg(b3  + pn);

        const float2 w1a = bcast2(W1.x), w1b = bcast2(W1.y);
        const float2 b1a = bcast2(B1.x), b1b = bcast2(B1.y);
        const float2 wA  = bcast2(W2.x), wB  = bcast2(W2.y);
        const float2 wC  = bcast2(W2.z), wD  = bcast2(W2.w);
        const float2 b2a = bcast2(B2.x), b2b = bcast2(B2.y);
        const float2 w3a = bcast2(W3.x), w3b = bcast2(W3.y);

        const float* xrow = &xs[(i_lo + ii) * BTILE];

        // 2x LDS.128 (warp-uniform broadcast, 32B-aligned) instead of 4x LDS.64
        const float4 xq0 = *(const float4*)(xrow);
        const float4 xq1 = *(const float4*)(xrow + 4);
        float2 xv[NPAIR];
        xv[0] = make_float2(xq0.x, xq0.y);
        xv[1] = make_float2(xq0.z, xq0.w);
        xv[2] = make_float2(xq1.x, xq1.y);
        xv[3] = make_float2(xq1.z, xq1.w);

        #pragma unroll
        for (int j = 0; j < NPAIR; j++) {
            float2 t0 = relu2(ffma2(xv[j], w1a, b1a));
            float2 t1 = relu2(ffma2(xv[j], w1b, b1b));
            float2 u0 = relu2(ffma2(t0, wA, ffma2(t1, wB, b2a)));
            float2 u1 = relu2(ffma2(t0, wC, ffma2(t1, wD, b2b)));
            acc[j] = ffma2(u0, w3a, ffma2(u1, w3b, acc[j]));
        }
    }

    // Fold this i-quarter's b3 sum into each batch element's partial.
    float* pq = &part[q * BTILE * OUTS];
    #pragma unroll
    for (int j = 0; j < NPAIR; j++) {
        pq[(2 * j)     * OUTS + o] = acc[j].x + sb3;
        pq[(2 * j + 1) * OUTS + o] = acc[j].y + sb3;
    }
    __syncthreads();

    // Reduce the four i-quarters; vectorized coalesced store.
    {
        const float2* p2 = (const float2*)part;
        float2 a = p2[tid];
        float2 b = p2[256 + tid];
        float2 c = p2[512 + tid];
        float2 d = p2[768 + tid];
        float2 r;
        r.x = (a.x + b.x) + (c.x + d.x);
        r.y = (a.y + b.y) + (c.y + d.y);
        *(float2*)&out[b0 * OUTS + 2 * tid] = r;
    }
}

extern "C" void kernel_launch(void* const* d_in, const int* in_sizes, int n_in,
                              void* d_out, int out_size)
{
    const float* x  = (const float*)d_in[0];
    const float* w1 = (const float*)d_in[1];
    const float* b1 = (const float*)d_in[2];
    const float* w2 = (const float*)d_in[3];
    const float* b2 = (const float*)d_in[4];
    const float* w3 = (const float*)d_in[5];
    const float* b3 = (const float*)d_in[6];
    float* out = (float*)d_out;

    kan_kernel<<<BATCH / BTILE, 256>>>(x, w1, b1, w2, b2, w3, b3, out);
}